// round 12
// baseline (speedup 1.0000x reference)
#include <cuda_runtime.h>
#include <cuda_fp16.h>
#include <cstdint>
#include <cstddef>

#define VOCAB 32000
#define DIM   512
#define SQ    2048
#define BATCH 64

// ---------------- static device scratch ----------------
__device__ float  g_XB[(size_t)SQ * BATCH * DIM];   // input term (fp32), row = t*64+b
__device__ __half g_YS[(size_t)SQ * BATCH * DIM];   // layer-0 outputs (fp16)
__device__ __half g_H[2][BATCH * DIM];              // ping-pong hidden state (fp16)
__device__ __half g_WihH[2][DIM * DIM];
__device__ __half g_WhhH[2][DIM * DIM];
__device__ float  g_bias[2][DIM];                   // b_ih + b_hh
__device__ unsigned g_bar_count = 0;
__device__ unsigned g_bar_epoch = 0;

// ---------------- mma / ldmatrix helpers ----------------
__device__ __forceinline__ void mma_16816(float* c, const uint32_t* a, const uint32_t* b) {
    asm volatile(
        "mma.sync.aligned.m16n8k16.row.col.f32.f16.f16.f32 "
        "{%0,%1,%2,%3}, {%4,%5,%6,%7}, {%8,%9}, {%0,%1,%2,%3};\n"
        : "+f"(c[0]), "+f"(c[1]), "+f"(c[2]), "+f"(c[3])
        : "r"(a[0]), "r"(a[1]), "r"(a[2]), "r"(a[3]), "r"(b[0]), "r"(b[1]));
}
__device__ __forceinline__ void ldsm_x4(uint32_t* r, uint32_t saddr) {
    asm volatile("ldmatrix.sync.aligned.m8n8.x4.shared.b16 {%0,%1,%2,%3}, [%4];"
                 : "=r"(r[0]), "=r"(r[1]), "=r"(r[2]), "=r"(r[3]) : "r"(saddr));
}
__device__ __forceinline__ uint32_t smem_u32(const void* p) {
    return (uint32_t)__cvta_generic_to_shared(p);
}

// ---------------- weight conversion ----------------
__global__ void convert_weights(const float* __restrict__ Wih,
                                const float* __restrict__ Whh,
                                const float* __restrict__ bih,
                                const float* __restrict__ bhh) {
    const int total = 2 * DIM * DIM;
    for (int j = blockIdx.x * blockDim.x + threadIdx.x; j < total;
         j += gridDim.x * blockDim.x) {
        ((__half*)g_WihH)[j] = __float2half_rn(Wih[j]);
        ((__half*)g_WhhH)[j] = __float2half_rn(Whh[j]);
    }
    const int i = blockIdx.x * blockDim.x + threadIdx.x;
    if (i < 2 * DIM) ((float*)g_bias)[i] = bih[i] + bhh[i];
}

// ---------------- xb GEMM: g_XB = A @ W_ih^T + bias ----------------
// A row r = t*64+b : layer0 -> embed[src[b][t]] (f32, convert), layer1 -> g_YS[r] (f16)
#define SPAD 8
#define SW (32 + SPAD)

__global__ void __launch_bounds__(256) xb_gemm(const float* __restrict__ embed,
                                               const int* __restrict__ src,
                                               int layer, int gather) {
    __shared__ __half As[128][SW];
    __shared__ __half Bs[128][SW];

    const __half* __restrict__ W    = g_WihH[layer];
    const float*  __restrict__ bias = g_bias[layer];

    const int m0 = blockIdx.y * 128, n0 = blockIdx.x * 128;
    const int tid = threadIdx.x, lane = tid & 31, warp = tid >> 5;
    const int wm = warp >> 2, wn = warp & 3;   // 2 x 4 warp grid (64x32 per warp)

    // loader: 2 threads per row, 16 halves (or floats) each
    const int lr = tid >> 1;
    const int lc = (tid & 1) * 16;
    const float*  aF = nullptr;
    const __half* aH = nullptr;
    if (gather) {
        const int r = m0 + lr, t = r >> 6, b = r & 63;
        aF = embed + (size_t)src[b * SQ + t] * DIM;
    } else {
        aH = g_YS + (size_t)(m0 + lr) * DIM;
    }
    const __half* bP = W + (size_t)(n0 + lr) * DIM;

    float acc[4][4][4];
#pragma unroll
    for (int i = 0; i < 4; i++)
#pragma unroll
        for (int j = 0; j < 4; j++)
#pragma unroll
            for (int q = 0; q < 4; q++) acc[i][j][q] = 0.f;

    // lane-dependent ldmatrix bases
    const uint32_t aBase = smem_u32(&As[wm * 64 + (lane & 15)][(lane >> 4) * 8]);
    const uint32_t bBase = smem_u32(&Bs[wn * 32 + ((lane >> 4) & 1) * 8 + (lane & 7)]
                                       [((lane >> 3) & 1) * 8]);

    for (int k0 = 0; k0 < DIM; k0 += 32) {
        __syncthreads();
        // ---- load A tile ----
        if (gather) {
            const float* p = aF + k0 + lc;
            float4 f0 = *(const float4*)(p);
            float4 f1 = *(const float4*)(p + 4);
            float4 f2 = *(const float4*)(p + 8);
            float4 f3 = *(const float4*)(p + 12);
            __half2* d = (__half2*)&As[lr][lc];
            d[0] = __floats2half2_rn(f0.x, f0.y);
            d[1] = __floats2half2_rn(f0.z, f0.w);
            d[2] = __floats2half2_rn(f1.x, f1.y);
            d[3] = __floats2half2_rn(f1.z, f1.w);
            d[4] = __floats2half2_rn(f2.x, f2.y);
            d[5] = __floats2half2_rn(f2.z, f2.w);
            d[6] = __floats2half2_rn(f3.x, f3.y);
            d[7] = __floats2half2_rn(f3.z, f3.w);
        } else {
            const uint4* p = (const uint4*)(aH + k0 + lc);
            *(uint4*)&As[lr][lc]     = p[0];
            *(uint4*)&As[lr][lc + 8] = p[1];
        }
        // ---- load B tile ----
        {
            const uint4* p = (const uint4*)(bP + k0 + lc);
            *(uint4*)&Bs[lr][lc]     = p[0];
            *(uint4*)&Bs[lr][lc + 8] = p[1];
        }
        __syncthreads();

        // ---- compute ----
#pragma unroll
        for (int h = 0; h < 2; h++) {
            uint32_t af[4][4];
#pragma unroll
            for (int i = 0; i < 4; i++)
                ldsm_x4(af[i], aBase + (i * 16 * SW + h * 16) * 2);
            uint32_t bf[2][4];
#pragma unroll
            for (int j2 = 0; j2 < 2; j2++)
                ldsm_x4(bf[j2], bBase + (j2 * 16 * SW + h * 16) * 2);
#pragma unroll
            for (int i = 0; i < 4; i++)
#pragma unroll
                for (int j = 0; j < 4; j++)
                    mma_16816(acc[i][j], af[i], &bf[j >> 1][(j & 1) * 2]);
        }
    }

    // ---- epilogue: add bias, store fp32 ----
#pragma unroll
    for (int i = 0; i < 4; i++) {
        const int row = m0 + wm * 64 + i * 16 + (lane >> 2);
#pragma unroll
        for (int j = 0; j < 4; j++) {
            const int col = n0 + wn * 32 + j * 8 + (lane & 3) * 2;
            const float2 bv = *(const float2*)&bias[col];
            float2 v0, v1;
            v0.x = acc[i][j][0] + bv.x; v0.y = acc[i][j][1] + bv.y;
            v1.x = acc[i][j][2] + bv.x; v1.y = acc[i][j][3] + bv.y;
            *(float2*)&g_XB[(size_t)row * DIM + col]       = v0;
            *(float2*)&g_XB[(size_t)(row + 8) * DIM + col] = v1;
        }
    }
}

// ---------------- persistent recurrence kernel ----------------
#define HPAD 8
#define HW (DIM + HPAD)

__global__ void __launch_bounds__(128, 1) rnn_kernel(int layer, float* __restrict__ out) {
    __shared__ __half hs[16][HW];

    const int c = blockIdx.x;
    const int mg = c >> 4, ng = c & 15;
    const int m0 = mg * 16, n0c = ng * 32;
    const int tid = threadIdx.x, lane = tid & 31, warp = tid >> 5;
    const int n0 = n0c + warp * 8;

    // preload W_hh fragments for this warp's 8 output columns (all K) into regs
    uint32_t wb[64];
    {
        const __half* Wp = g_WhhH[layer] + (size_t)(n0 + (lane >> 2)) * DIM + (lane & 3) * 2;
#pragma unroll
        for (int kt = 0; kt < 32; kt++) {
            wb[kt * 2 + 0] = *(const uint32_t*)(Wp + kt * 16);
            wb[kt * 2 + 1] = *(const uint32_t*)(Wp + kt * 16 + 8);
        }
    }

    const unsigned e0 = *(volatile unsigned*)&g_bar_epoch;   // quiescent at launch
    unsigned c0 = 0;
    if (tid == 0) c0 = *(volatile unsigned*)&g_bar_count;

    const uint32_t aBase = smem_u32(&hs[lane & 15][(lane >> 4) * 8]);
    const int er = lane >> 2, ec = (lane & 3) * 2;
    const int r0 = m0 + er, r1 = r0 + 8, col = n0 + ec;

    for (int t = 0; t < SQ; t++) {
        const int p = t & 1;
        float acc[4][4];
#pragma unroll
        for (int q = 0; q < 4; q++)
#pragma unroll
            for (int w4 = 0; w4 < 4; w4++) acc[q][w4] = 0.f;

        if (t > 0) {
            // stage h slice (rows m0..m0+15) from L2, bypassing L1
#pragma unroll
            for (int j = 0; j < 8; j++) {
                const int idx = tid + j * 128;          // 0..1023
                const int r = idx >> 6, c8 = (idx & 63) * 8;
                *(uint4*)&hs[r][c8] =
                    __ldcg((const uint4*)&g_H[p][(m0 + r) * DIM + c8]);
            }
            __syncthreads();
#pragma unroll
            for (int kt = 0; kt < 32; kt++) {
                uint32_t a[4];
                ldsm_x4(a, aBase + kt * 32);            // 16 halves = 32 bytes per k-tile
                mma_16816(acc[kt & 3], a, &wb[kt * 2]);
            }
        }
#pragma unroll
        for (int q = 1; q < 4; q++)
#pragma unroll
            for (int w4 = 0; w4 < 4; w4++) acc[0][w4] += acc[q][w4];

        // epilogue: h = tanh(xb + acc)
        const size_t xoff = ((size_t)t * BATCH + r0) * DIM + col;
        const float2 x0 = *(const float2*)&g_XB[xoff];
        const float2 x1 = *(const float2*)&g_XB[xoff + 8 * DIM];
        const float v0 = tanhf(x0.x + acc[0][0]);
        const float v1 = tanhf(x0.y + acc[0][1]);
        const float v2 = tanhf(x1.x + acc[0][2]);
        const float v3 = tanhf(x1.y + acc[0][3]);

        const int np = p ^ 1;
        const __half2 h01 = __floats2half2_rn(v0, v1);
        const __half2 h23 = __floats2half2_rn(v2, v3);
        __stcg((__half2*)&g_H[np][r0 * DIM + col], h01);
        __stcg((__half2*)&g_H[np][r1 * DIM + col], h23);
        if (layer == 0) {
            *(__half2*)&g_YS[((size_t)t * BATCH + r0) * DIM + col] = h01;
            *(__half2*)&g_YS[((size_t)t * BATCH + r1) * DIM + col] = h23;
        }
        if (t == SQ - 1) {
            *(float2*)&out[layer * BATCH * DIM + r0 * DIM + col] = make_float2(v0, v1);
            *(float2*)&out[layer * BATCH * DIM + r1 * DIM + col] = make_float2(v2, v3);
        }

        // grid barrier (monotonic counters: graph-replay safe, no reset race)
        __threadfence();
        __syncthreads();
        if (tid == 0) {
            const unsigned old = atomicAdd(&g_bar_count, 1u);
            if (old == c0 + 64u * (unsigned)(t + 1) - 1u) {
                atomicAdd(&g_bar_epoch, 1u);
            } else {
                while (*(volatile unsigned*)&g_bar_epoch - e0 < (unsigned)(t + 1))
                    __nanosleep(64);
            }
        }
        __syncthreads();
        __threadfence();
    }
}

// ---------------- launch ----------------
extern "C" void kernel_launch(void* const* d_in, const int* in_sizes, int n_in,
                              void* d_out, int out_size) {
    const int*   src   = (const int*)d_in[0];
    const float* embed = (const float*)d_in[1];
    const float* Wih   = (const float*)d_in[2];
    const float* Whh   = (const float*)d_in[3];
    const float* bih   = (const float*)d_in[4];
    const float* bhh   = (const float*)d_in[5];
    float* out = (float*)d_out;

    convert_weights<<<512, 256>>>(Wih, Whh, bih, bhh);

    dim3 ggrid(DIM / 128, (SQ * BATCH) / 128);   // (4, 1024)
    xb_gemm<<<ggrid, 256>>>(embed, src, 0, 1);
    rnn_kernel<<<64, 128>>>(0, out);
    xb_gemm<<<ggrid, 256>>>(nullptr, nullptr, 1, 0);
    rnn_kernel<<<64, 128>>>(1, out);
}

// round 13
// speedup vs baseline: 1.0124x; 1.0124x over previous
#include <cuda_runtime.h>
#include <cuda_fp16.h>
#include <cstdint>
#include <cstddef>

#define VOCAB 32000
#define DIM   512
#define SQ    2048
#define BATCH 64

// ---------------- static device scratch ----------------
__device__ float  g_XB[(size_t)SQ * BATCH * DIM];   // input term (fp32), row = t*64+b
__device__ __half g_YS[(size_t)SQ * BATCH * DIM];   // layer-0 outputs (fp16)
__device__ __half g_H[2][BATCH * DIM];              // ping-pong hidden state (fp16)
__device__ __half g_WihH[2][DIM * DIM];
__device__ __half g_WhhH[2][DIM * DIM];
__device__ float  g_bias[2][DIM];                   // b_ih + b_hh
__device__ unsigned g_bar_count = 0;
__device__ unsigned g_bar_epoch = 0;

// ---------------- mma / ldmatrix helpers ----------------
__device__ __forceinline__ void mma_16816(float* c, const uint32_t* a, const uint32_t* b) {
    asm volatile(
        "mma.sync.aligned.m16n8k16.row.col.f32.f16.f16.f32 "
        "{%0,%1,%2,%3}, {%4,%5,%6,%7}, {%8,%9}, {%0,%1,%2,%3};\n"
        : "+f"(c[0]), "+f"(c[1]), "+f"(c[2]), "+f"(c[3])
        : "r"(a[0]), "r"(a[1]), "r"(a[2]), "r"(a[3]), "r"(b[0]), "r"(b[1]));
}
__device__ __forceinline__ void ldsm_x4(uint32_t* r, uint32_t saddr) {
    asm volatile("ldmatrix.sync.aligned.m8n8.x4.shared.b16 {%0,%1,%2,%3}, [%4];"
                 : "=r"(r[0]), "=r"(r[1]), "=r"(r[2]), "=r"(r[3]) : "r"(saddr));
}
__device__ __forceinline__ uint32_t smem_u32(const void* p) {
    return (uint32_t)__cvta_generic_to_shared(p);
}

// ---------------- weight conversion ----------------
__global__ void convert_weights(const float* __restrict__ Wih,
                                const float* __restrict__ Whh,
                                const float* __restrict__ bih,
                                const float* __restrict__ bhh) {
    const int total = 2 * DIM * DIM;
    for (int j = blockIdx.x * blockDim.x + threadIdx.x; j < total;
         j += gridDim.x * blockDim.x) {
        ((__half*)g_WihH)[j] = __float2half_rn(Wih[j]);
        ((__half*)g_WhhH)[j] = __float2half_rn(Whh[j]);
    }
    const int i = blockIdx.x * blockDim.x + threadIdx.x;
    if (i < 2 * DIM) ((float*)g_bias)[i] = bih[i] + bhh[i];
}

// ---------------- xb GEMM: g_XB = A @ W_ih^T + bias ----------------
// A row r = t*64+b : layer0 -> embed[src[b][t]] (f32, convert), layer1 -> g_YS[r] (f16)
#define SPAD 8
#define SW (32 + SPAD)

__global__ void __launch_bounds__(256) xb_gemm(const float* __restrict__ embed,
                                               const int* __restrict__ src,
                                               int layer, int gather) {
    __shared__ __half As[128][SW];
    __shared__ __half Bs[128][SW];

    const __half* __restrict__ W    = g_WihH[layer];
    const float*  __restrict__ bias = g_bias[layer];

    const int m0 = blockIdx.y * 128, n0 = blockIdx.x * 128;
    const int tid = threadIdx.x, lane = tid & 31, warp = tid >> 5;
    const int wm = warp >> 2, wn = warp & 3;   // 2 x 4 warp grid (64x32 per warp)

    // loader: 2 threads per row, 16 halves (or floats) each
    const int lr = tid >> 1;
    const int lc = (tid & 1) * 16;
    const float*  aF = nullptr;
    const __half* aH = nullptr;
    if (gather) {
        const int r = m0 + lr, t = r >> 6, b = r & 63;
        aF = embed + (size_t)src[b * SQ + t] * DIM;
    } else {
        aH = g_YS + (size_t)(m0 + lr) * DIM;
    }
    const __half* bP = W + (size_t)(n0 + lr) * DIM;

    float acc[4][4][4];
#pragma unroll
    for (int i = 0; i < 4; i++)
#pragma unroll
        for (int j = 0; j < 4; j++)
#pragma unroll
            for (int q = 0; q < 4; q++) acc[i][j][q] = 0.f;

    // lane-dependent ldmatrix bases
    const uint32_t aBase = smem_u32(&As[wm * 64 + (lane & 15)][(lane >> 4) * 8]);
    const uint32_t bBase = smem_u32(&Bs[wn * 32 + ((lane >> 4) & 1) * 8 + (lane & 7)]
                                       [((lane >> 3) & 1) * 8]);

    for (int k0 = 0; k0 < DIM; k0 += 32) {
        __syncthreads();
        // ---- load A tile ----
        if (gather) {
            const float* p = aF + k0 + lc;
            float4 f0 = *(const float4*)(p);
            float4 f1 = *(const float4*)(p + 4);
            float4 f2 = *(const float4*)(p + 8);
            float4 f3 = *(const float4*)(p + 12);
            __half2* d = (__half2*)&As[lr][lc];
            d[0] = __floats2half2_rn(f0.x, f0.y);
            d[1] = __floats2half2_rn(f0.z, f0.w);
            d[2] = __floats2half2_rn(f1.x, f1.y);
            d[3] = __floats2half2_rn(f1.z, f1.w);
            d[4] = __floats2half2_rn(f2.x, f2.y);
            d[5] = __floats2half2_rn(f2.z, f2.w);
            d[6] = __floats2half2_rn(f3.x, f3.y);
            d[7] = __floats2half2_rn(f3.z, f3.w);
        } else {
            const uint4* p = (const uint4*)(aH + k0 + lc);
            *(uint4*)&As[lr][lc]     = p[0];
            *(uint4*)&As[lr][lc + 8] = p[1];
        }
        // ---- load B tile ----
        {
            const uint4* p = (const uint4*)(bP + k0 + lc);
            *(uint4*)&Bs[lr][lc]     = p[0];
            *(uint4*)&Bs[lr][lc + 8] = p[1];
        }
        __syncthreads();

        // ---- compute ----
#pragma unroll
        for (int h = 0; h < 2; h++) {
            uint32_t af[4][4];
#pragma unroll
            for (int i = 0; i < 4; i++)
                ldsm_x4(af[i], aBase + (i * 16 * SW + h * 16) * 2);
            uint32_t bf[2][4];
#pragma unroll
            for (int j2 = 0; j2 < 2; j2++)
                ldsm_x4(bf[j2], bBase + (j2 * 16 * SW + h * 16) * 2);
#pragma unroll
            for (int i = 0; i < 4; i++)
#pragma unroll
                for (int j = 0; j < 4; j++)
                    mma_16816(acc[i][j], af[i], &bf[j >> 1][(j & 1) * 2]);
        }
    }

    // ---- epilogue: add bias, store fp32 ----
#pragma unroll
    for (int i = 0; i < 4; i++) {
        const int row = m0 + wm * 64 + i * 16 + (lane >> 2);
#pragma unroll
        for (int j = 0; j < 4; j++) {
            const int col = n0 + wn * 32 + j * 8 + (lane & 3) * 2;
            const float2 bv = *(const float2*)&bias[col];
            float2 v0, v1;
            v0.x = acc[i][j][0] + bv.x; v0.y = acc[i][j][1] + bv.y;
            v1.x = acc[i][j][2] + bv.x; v1.y = acc[i][j][3] + bv.y;
            *(float2*)&g_XB[(size_t)row * DIM + col]       = v0;
            *(float2*)&g_XB[(size_t)(row + 8) * DIM + col] = v1;
        }
    }
}

// ---------------- persistent recurrence kernel ----------------
#define HPAD 8
#define HW (DIM + HPAD)

__global__ void __launch_bounds__(128, 1) rnn_kernel(int layer, float* __restrict__ out) {
    __shared__ __half hs[16][HW];

    const int c = blockIdx.x;
    const int mg = c >> 4, ng = c & 15;
    const int m0 = mg * 16, n0c = ng * 32;
    const int tid = threadIdx.x, lane = tid & 31, warp = tid >> 5;
    const int n0 = n0c + warp * 8;

    // preload W_hh fragments for this warp's 8 output columns (all K) into regs
    uint32_t wb[64];
    {
        const __half* Wp = g_WhhH[layer] + (size_t)(n0 + (lane >> 2)) * DIM + (lane & 3) * 2;
#pragma unroll
        for (int kt = 0; kt < 32; kt++) {
            wb[kt * 2 + 0] = *(const uint32_t*)(Wp + kt * 16);
            wb[kt * 2 + 1] = *(const uint32_t*)(Wp + kt * 16 + 8);
        }
    }

    const unsigned e0 = *(volatile unsigned*)&g_bar_epoch;   // quiescent at launch
    unsigned c0 = 0;
    if (tid == 0) c0 = *(volatile unsigned*)&g_bar_count;

    const uint32_t aBase = smem_u32(&hs[lane & 15][(lane >> 4) * 8]);
    const int er = lane >> 2, ec = (lane & 3) * 2;
    const int r0 = m0 + er, r1 = r0 + 8, col = n0 + ec;

    for (int t = 0; t < SQ; t++) {
        const int p = t & 1;
        float acc[4][4];
#pragma unroll
        for (int q = 0; q < 4; q++)
#pragma unroll
            for (int w4 = 0; w4 < 4; w4++) acc[q][w4] = 0.f;

        if (t > 0) {
            // stage h slice (rows m0..m0+15) from L2, bypassing L1
#pragma unroll
            for (int j = 0; j < 8; j++) {
                const int idx = tid + j * 128;          // 0..1023
                const int r = idx >> 6, c8 = (idx & 63) * 8;
                *(uint4*)&hs[r][c8] =
                    __ldcg((const uint4*)&g_H[p][(m0 + r) * DIM + c8]);
            }
            __syncthreads();
#pragma unroll
            for (int kt = 0; kt < 32; kt++) {
                uint32_t a[4];
                ldsm_x4(a, aBase + kt * 32);            // 16 halves = 32 bytes per k-tile
                mma_16816(acc[kt & 3], a, &wb[kt * 2]);
            }
        }
#pragma unroll
        for (int q = 1; q < 4; q++)
#pragma unroll
            for (int w4 = 0; w4 < 4; w4++) acc[0][w4] += acc[q][w4];

        // epilogue: h = tanh(xb + acc)
        const size_t xoff = ((size_t)t * BATCH + r0) * DIM + col;
        const float2 x0 = *(const float2*)&g_XB[xoff];
        const float2 x1 = *(const float2*)&g_XB[xoff + 8 * DIM];
        const float v0 = tanhf(x0.x + acc[0][0]);
        const float v1 = tanhf(x0.y + acc[0][1]);
        const float v2 = tanhf(x1.x + acc[0][2]);
        const float v3 = tanhf(x1.y + acc[0][3]);

        const int np = p ^ 1;
        const __half2 h01 = __floats2half2_rn(v0, v1);
        const __half2 h23 = __floats2half2_rn(v2, v3);
        __stcg((__half2*)&g_H[np][r0 * DIM + col], h01);
        __stcg((__half2*)&g_H[np][r1 * DIM + col], h23);
        if (layer == 0) {
            *(__half2*)&g_YS[((size_t)t * BATCH + r0) * DIM + col] = h01;
            *(__half2*)&g_YS[((size_t)t * BATCH + r1) * DIM + col] = h23;
        }
        if (t == SQ - 1) {
            *(float2*)&out[layer * BATCH * DIM + r0 * DIM + col] = make_float2(v0, v1);
            *(float2*)&out[layer * BATCH * DIM + r1 * DIM + col] = make_float2(v2, v3);
        }

        // grid barrier (monotonic counters: graph-replay safe, no reset race)
        __threadfence();
        __syncthreads();
        if (tid == 0) {
            const unsigned old = atomicAdd(&g_bar_count, 1u);
            if (old == c0 + 64u * (unsigned)(t + 1) - 1u) {
                atomicAdd(&g_bar_epoch, 1u);
            } else {
                while (*(volatile unsigned*)&g_bar_epoch - e0 < (unsigned)(t + 1))
                    __nanosleep(64);
            }
        }
        __syncthreads();
        __threadfence();
    }
}

// ---------------- launch ----------------
extern "C" void kernel_launch(void* const* d_in, const int* in_sizes, int n_in,
                              void* d_out, int out_size) {
    const int*   src   = (const int*)d_in[0];
    const float* embed = (const float*)d_in[1];
    const float* Wih   = (const float*)d_in[2];
    const float* Whh   = (const float*)d_in[3];
    const float* bih   = (const float*)d_in[4];
    const float* bhh   = (const float*)d_in[5];
    float* out = (float*)d_out;

    convert_weights<<<512, 256>>>(Wih, Whh, bih, bhh);

    dim3 ggrid(DIM / 128, (SQ * BATCH) / 128);   // (4, 1024)
    xb_gemm<<<ggrid, 256>>>(embed, src, 0, 1);
    rnn_kernel<<<64, 128>>>(0, out);
    xb_gemm<<<ggrid, 256>>>(nullptr, nullptr, 1, 0);
    rnn_kernel<<<64, 128>>>(1, out);
}